// round 1
// baseline (speedup 1.0000x reference)
#include <cuda_runtime.h>

#define BS    32
#define NTOK  512
#define DM    96
#define A2LEN 150
#define NTOT  (BS*NTOK)   // 16384

// ---------------- scratch (device globals; no allocation allowed) ----------
__device__ float g_y [NTOT * 288];   // qkv output
__device__ float g_sp[NTOT * 40];    // sparse attn out (b channels 32..72)
__device__ float g_dn[BS * A2LEN * 24]; // dense attn out (b channels 72..96, a2a rows)
__device__ int   g_inv[NTOK];        // token -> a2a index (or -1)

// ---------------- f32x2 helpers --------------------------------------------
__device__ __forceinline__ void ffma2(unsigned long long& d,
                                      unsigned long long a,
                                      unsigned long long b) {
    asm("fma.rn.f32x2 %0, %1, %2, %0;" : "+l"(d) : "l"(a), "l"(b));
}
__device__ __forceinline__ unsigned long long bcast2(float v) {
    unsigned long long r; unsigned int u = __float_as_uint(v);
    asm("mov.b64 %0, {%1, %1};" : "=l"(r) : "r"(u));
    return r;
}
__device__ __forceinline__ unsigned long long addf2(unsigned long long a,
                                                    unsigned long long b) {
    unsigned long long r;
    asm("add.rn.f32x2 %0, %1, %2;" : "=l"(r) : "l"(a), "l"(b));
    return r;
}

// ---------------- K1: y = x @ Wqv^T + bias  (16384 x 288, K=96) ------------
// grid (256, 3), 256 threads. Tile: 64 tokens x 96 outputs, full K.
// smem: sX [64][97] row-major (t,k); sW [96][98] (k,o) transposed; sB[96].
__global__ void __launch_bounds__(256) k_qkv(const float* __restrict__ x,
                                             const float* __restrict__ W) {
    extern __shared__ __align__(16) float sm[];
    float* sX = sm;                 // 64*97 = 6208
    float* sW = sm + 64*97;         // 96*98 = 9408
    float* sB = sW + 96*98;         // 96
    const int t0 = blockIdx.x * 64;
    const int o0 = blockIdx.y * 96;
    const int tid = threadIdx.x;

    for (int i = tid; i < 64*96; i += 256) {
        int t = i / 96, k = i - t*96;
        sX[t*97 + k] = x[(t0 + t)*96 + k];          // coalesced read, clean write
    }
    for (int i = tid; i < 96*96; i += 256) {
        int o = i / 96, k = i - o*96;
        sW[k*98 + o] = W[(o0 + o)*97 + k];          // coalesced read
    }
    if (tid < 96) sB[tid] = W[(o0 + tid)*97 + 96];
    __syncthreads();

    const int tb = (tid & 15) * 4;   // token base (4 tokens)
    const int ob = (tid >> 4) * 6;   // output base (6 outputs = 3 pairs)
    unsigned long long acc[4][3];
#pragma unroll
    for (int j = 0; j < 3; j++) {
        unsigned long long bv = *(const unsigned long long*)&sB[ob + 2*j];
        acc[0][j] = bv; acc[1][j] = bv; acc[2][j] = bv; acc[3][j] = bv;
    }
#pragma unroll 8
    for (int k = 0; k < 96; k++) {
        unsigned long long x2[4];
#pragma unroll
        for (int t = 0; t < 4; t++) x2[t] = bcast2(sX[(tb + t)*97 + k]);
        const unsigned long long* wrow =
            (const unsigned long long*)&sW[k*98 + ob];
        unsigned long long w0 = wrow[0], w1 = wrow[1], w2 = wrow[2];
#pragma unroll
        for (int t = 0; t < 4; t++) {
            ffma2(acc[t][0], x2[t], w0);
            ffma2(acc[t][1], x2[t], w1);
            ffma2(acc[t][2], x2[t], w2);
        }
    }
#pragma unroll
    for (int t = 0; t < 4; t++)
#pragma unroll
        for (int j = 0; j < 3; j++)
            *(unsigned long long*)&g_y[(t0 + tb + t)*288 + o0 + ob + 2*j] = acc[t][j];
}

// ---------------- K0: inverse a2a map ---------------------------------------
__global__ void k_inv(const int* __restrict__ a2a) {
    int t = threadIdx.x;           // 512 threads
    g_inv[t] = -1;
    __syncthreads();
    if (t < A2LEN) g_inv[a2a[t]] = t;
}

// ---------------- K3: sparse L1 attention (both coo sets) -------------------
// grid 256 = (b, set i, head h); 256 threads; 2 tokens per thread.
__global__ void __launch_bounds__(256) k_sparse(const int* __restrict__ coo0,
                                                const int* __restrict__ coo1) {
    const int bx = blockIdx.x;
    const int b = bx >> 3;
    const int i = (bx >> 2) & 1;
    const int h = bx & 3;
    const int qc = 32 + 20*i + h*5;          // q channel base; k:+96, v:+192
    __shared__ float sK[NTOK*5];
    __shared__ float sV[NTOK*5];
    const int tid = threadIdx.x;
    for (int idx = tid; idx < NTOK*5; idx += 256) {
        int tok = idx / 5, w = idx - tok*5;
        const float* base = &g_y[(b*NTOK + tok)*288];
        sK[idx] = base[ 96 + qc + w];
        sV[idx] = base[192 + qc + w];
    }
    __syncthreads();
    const int* coo = i ? coo1 : coo0;
    const float scale = 0.44721359549995793f;   // 1/sqrt(5)
    for (int t = tid; t < NTOK; t += 256) {
        const float* qp = &g_y[(b*NTOK + t)*288 + qc];
        float q0 = qp[0], q1 = qp[1], q2 = qp[2], q3 = qp[3], q4 = qp[4];
        int srcs[32]; float logit[32];
        float m = -1e30f;
#pragma unroll
        for (int r = 0; r < 32; r++) {
            int src = coo[(t*32 + r)*3 + 1];
            srcs[r] = src;
            const float* kp = &sK[src*5];
            float s = fabsf(q0 - kp[0]) + fabsf(q1 - kp[1]) + fabsf(q2 - kp[2])
                    + fabsf(q3 - kp[3]) + fabsf(q4 - kp[4]);
            float lg = -s * scale;
            logit[r] = lg;
            m = fmaxf(m, lg);
        }
        float l = 0.f, a0 = 0.f, a1 = 0.f, a2 = 0.f, a3 = 0.f, a4 = 0.f;
#pragma unroll
        for (int r = 0; r < 32; r++) {
            float p = __expf(logit[r] - m);
            l += p;
            const float* vp = &sV[srcs[r]*5];
            a0 += p*vp[0]; a1 += p*vp[1]; a2 += p*vp[2]; a3 += p*vp[3]; a4 += p*vp[4];
        }
        float inv = 1.0f / l;
        float* op = &g_sp[(b*NTOK + t)*40 + i*20 + h*5];
        op[0] = a0*inv; op[1] = a1*inv; op[2] = a2*inv; op[3] = a3*inv; op[4] = a4*inv;
    }
}

// ---------------- K4: dense a2a L1 attention --------------------------------
// One block per batch; thread = (d, h), d<150, h<4. Includes the zero-pad key
// in the softmax denominator (row s=150 of the padded softmax).
__global__ void __launch_bounds__(640) k_dense(const int* __restrict__ a2a) {
    const int b = blockIdx.x;
    __shared__ float sK[A2LEN*24];
    __shared__ float sV[A2LEN*24];
    const int tid = threadIdx.x;
    for (int idx = tid; idx < A2LEN*24; idx += 640) {
        int s = idx / 24, c = idx - s*24;
        int tok = a2a[s];
        const float* base = &g_y[(b*NTOK + tok)*288];
        sK[idx] = base[168 + c];   // k channels 72..96 -> y 168..192
        sV[idx] = base[264 + c];   // v channels 72..96 -> y 264..288
    }
    __syncthreads();
    if (tid < 600) {
        int d = tid >> 2, h = tid & 3;
        int tok = a2a[d];
        const float* qp = &g_y[(b*NTOK + tok)*288 + 72 + h*6];
        float q[6];
#pragma unroll
        for (int w = 0; w < 6; w++) q[w] = qp[w];
        const float scale = 0.4082482904638631f;   // 1/sqrt(6)
        float m = -1e30f, l = 0.f;
        float acc[6] = {0.f,0.f,0.f,0.f,0.f,0.f};
        for (int s = 0; s < A2LEN; s++) {
            const float* kp = &sK[s*24 + h*6];
            float ds = 0.f;
#pragma unroll
            for (int w = 0; w < 6; w++) ds += fabsf(q[w] - kp[w]);
            float lg = -ds * scale;
            float nm = fmaxf(m, lg);
            float f  = __expf(m - nm);
            float p  = __expf(lg - nm);
            l = l*f + p;
            const float* vp = &sV[s*24 + h*6];
#pragma unroll
            for (int w = 0; w < 6; w++) acc[w] = acc[w]*f + p*vp[w];
            m = nm;
        }
        // zero-pad key: in denominator only, no value contribution
        {
            float ds = 0.f;
#pragma unroll
            for (int w = 0; w < 6; w++) ds += fabsf(q[w]);
            float lg = -ds * scale;
            float nm = fmaxf(m, lg);
            float f  = __expf(m - nm);
            float p  = __expf(lg - nm);
            l = l*f + p;
#pragma unroll
            for (int w = 0; w < 6; w++) acc[w] *= f;
        }
        float inv = 1.0f / l;
        float* op = &g_dn[(b*A2LEN + d)*24 + h*6];
#pragma unroll
        for (int w = 0; w < 6; w++) op[w] = acc[w]*inv;
    }
}

// ---------------- K5: out = x + SiLU(b) @ Wf^T + bias ------------------------
// Only b channels 32..96 are nonzero (K=64). grid 256, 256 threads.
__global__ void __launch_bounds__(256) k_final(const float* __restrict__ x,
                                               const float* __restrict__ Wf,
                                               float* __restrict__ out) {
    __shared__ __align__(16) float sY[64*65];   // [t][c] stride 65
    __shared__ __align__(16) float sW[64*98];   // [c][o] stride 98
    __shared__ __align__(16) float sB[96];
    const int t0 = blockIdx.x * 64;
    const int tid = threadIdx.x;

    for (int idx = tid; idx < 64*96; idx += 256) {
        int o = idx / 64, c = idx - o*64;
        sW[c*98 + o] = Wf[o*97 + 32 + c];       // coalesced read (consecutive c)
    }
    if (tid < 96) sB[tid] = Wf[tid*97 + 96];
    for (int idx = tid; idx < 64*64; idx += 256) {
        int c = idx >> 6, t = idx & 63;
        int tt = t0 + t;
        float v;
        if (c < 40) {
            v = g_sp[tt*40 + c];
        } else {
            int b = tt >> 9, tok = tt & 511;
            int d = g_inv[tok];
            v = (d >= 0) ? g_dn[(b*A2LEN + d)*24 + (c - 40)] : 0.f;
        }
        float sg = 1.0f / (1.0f + __expf(-1.702f * v));
        sY[t*65 + c] = v * sg;
    }
    __syncthreads();

    const int tb = (tid & 15) * 4;
    const int ob = (tid >> 4) * 6;
    unsigned long long acc[4][3];
#pragma unroll
    for (int j = 0; j < 3; j++) {
        unsigned long long bv = *(const unsigned long long*)&sB[ob + 2*j];
        acc[0][j] = bv; acc[1][j] = bv; acc[2][j] = bv; acc[3][j] = bv;
    }
#pragma unroll 8
    for (int k = 0; k < 64; k++) {
        unsigned long long y2[4];
#pragma unroll
        for (int t = 0; t < 4; t++) y2[t] = bcast2(sY[(tb + t)*65 + k]);
        const unsigned long long* wrow =
            (const unsigned long long*)&sW[k*98 + ob];
        unsigned long long w0 = wrow[0], w1 = wrow[1], w2 = wrow[2];
#pragma unroll
        for (int t = 0; t < 4; t++) {
            ffma2(acc[t][0], y2[t], w0);
            ffma2(acc[t][1], y2[t], w1);
            ffma2(acc[t][2], y2[t], w2);
        }
    }
#pragma unroll
    for (int t = 0; t < 4; t++) {
        int tt = t0 + tb + t;
#pragma unroll
        for (int j = 0; j < 3; j++) {
            unsigned long long xv =
                *(const unsigned long long*)&x[tt*96 + ob + 2*j];
            *(unsigned long long*)&out[tt*96 + ob + 2*j] = addf2(acc[t][j], xv);
        }
    }
}

// ---------------- launch -----------------------------------------------------
extern "C" void kernel_launch(void* const* d_in, const int* in_sizes, int n_in,
                              void* d_out, int out_size) {
    const float* x    = (const float*)d_in[0];
    const float* wqv  = (const float*)d_in[1];
    const float* wf   = (const float*)d_in[2];
    const int*   coo0 = (const int*)d_in[3];
    const int*   coo1 = (const int*)d_in[4];
    const int*   a2a  = (const int*)d_in[5];
    float*       out  = (float*)d_out;
    (void)in_sizes; (void)n_in; (void)out_size;

    const size_t smem1 = (64*97 + 96*98 + 96) * sizeof(float);  // 62848 B
    cudaFuncSetAttribute(k_qkv, cudaFuncAttributeMaxDynamicSharedMemorySize,
                         (int)smem1);

    k_qkv  <<<dim3(256, 3), 256, smem1>>>(x, wqv);
    k_inv  <<<1, 512>>>(a2a);
    k_sparse<<<256, 256>>>(coo0, coo1);
    k_dense <<<32, 640>>>(a2a);
    k_final <<<256, 256>>>(x, wf, out);
}

// round 2
// speedup vs baseline: 1.2320x; 1.2320x over previous
#include <cuda_runtime.h>

#define BS    32
#define NTOK  512
#define DM    96
#define A2LEN 150
#define NTOT  (BS*NTOK)          // 16384
#define NDR   (BS*A2LEN)         // 4800 dense rows
#define YW    128                // compact y width (120 used + 8 pad)

// ---------------- scratch ----------------------------------------------------
__device__ float g_y  [NTOT * YW];        // compact qkv: [q32..72 | k32..72 | v32..72 | pad]
__device__ float g_yd [3 * NDR * 24];     // dense qkv planes: q,k,v (a2a rows only)
__device__ float g_sp [NTOT * 40];        // sparse attn out (b channels 32..72)
__device__ float g_dn [NDR * 24];         // dense attn out
__device__ int   g_inv[NTOK];             // token -> a2a index (or -1)
__device__ int   g_src[2 * NTOK * 32];    // transposed coo src: [i][r][t]

// ---------------- f32x2 helpers ----------------------------------------------
__device__ __forceinline__ void ffma2(unsigned long long& d,
                                      unsigned long long a,
                                      unsigned long long b) {
    asm("fma.rn.f32x2 %0, %1, %2, %0;" : "+l"(d) : "l"(a), "l"(b));
}
__device__ __forceinline__ unsigned long long bcast2(float v) {
    unsigned long long r; unsigned int u = __float_as_uint(v);
    asm("mov.b64 %0, {%1, %1};" : "=l"(r) : "r"(u));
    return r;
}
__device__ __forceinline__ unsigned long long addf2(unsigned long long a,
                                                    unsigned long long b) {
    unsigned long long r;
    asm("add.rn.f32x2 %0, %1, %2;" : "=l"(r) : "l"(a), "l"(b));
    return r;
}

// map compact output channel -> Wqv row
__device__ __forceinline__ int rowmap(int o) {
    if (o < 40)  return 32 + o;          // q ch 32..72
    if (o < 80)  return 88 + o;          // k ch 32..72 (rows 128..168)
    if (o < 120) return 144 + o;         // v ch 32..72 (rows 224..264)
    return 32;                           // pad (unused)
}

// ---------------- K_prep: transposed src + inverse a2a map --------------------
__global__ void k_prep(const int* __restrict__ coo0,
                       const int* __restrict__ coo1,
                       const int* __restrict__ a2a) {
    const int i = blockIdx.x;
    const int* coo = i ? coo1 : coo0;
    const int t = threadIdx.x;
    const int e = blockIdx.y * 512 + t;          // entry 0..16383
    int src = coo[e * 3 + 1];
    int tok = e >> 5, r = e & 31;
    g_src[i * 16384 + r * 512 + tok] = src;
    if (i == 0 && blockIdx.y == 0) {
        g_inv[t] = -1;
        __syncthreads();
        if (t < A2LEN) g_inv[a2a[t]] = t;
    }
}

// ---------------- K1: compact qkv GEMM (16384 x 128, K=96) --------------------
// grid (256, 2): 64-token x 64-output tile; 256 threads; thread = 4 tok x 4 out.
__global__ void __launch_bounds__(256) k_qkv(const float* __restrict__ x,
                                             const float* __restrict__ W) {
    extern __shared__ __align__(16) float sm[];
    float* sX = sm;                  // 64*97
    float* sW = sm + 64*97;          // 96*66
    float* sB = sW + 96*66;          // 64
    const int t0 = blockIdx.x * 64;
    const int o0 = blockIdx.y * 64;
    const int tid = threadIdx.x;

    for (int i = tid; i < 64*96; i += 256) {
        int t = i / 96, k = i - t*96;
        sX[t*97 + k] = x[(t0 + t)*96 + k];
    }
    for (int i = tid; i < 64*96; i += 256) {
        int o = i / 96, k = i - o*96;
        sW[k*66 + o] = W[rowmap(o0 + o)*97 + k];
    }
    if (tid < 64) sB[tid] = W[rowmap(o0 + tid)*97 + 96];
    __syncthreads();

    const int tokg = tid & 15;       // tokens: tokg + 16*t (conflict-free LDS)
    const int ob   = (tid >> 4) * 4; // 4 outputs = 2 f32x2 pairs
    unsigned long long acc[4][2];
#pragma unroll
    for (int j = 0; j < 2; j++) {
        unsigned long long bv = *(const unsigned long long*)&sB[ob + 2*j];
        acc[0][j] = bv; acc[1][j] = bv; acc[2][j] = bv; acc[3][j] = bv;
    }
#pragma unroll 8
    for (int k = 0; k < 96; k++) {
        unsigned long long w0 = *(const unsigned long long*)&sW[k*66 + ob];
        unsigned long long w1 = *(const unsigned long long*)&sW[k*66 + ob + 2];
#pragma unroll
        for (int t = 0; t < 4; t++) {
            unsigned long long xv = bcast2(sX[(tokg + 16*t)*97 + k]);
            ffma2(acc[t][0], xv, w0);
            ffma2(acc[t][1], xv, w1);
        }
    }
#pragma unroll
    for (int t = 0; t < 4; t++) {
        int tok = t0 + tokg + 16*t;
        *(unsigned long long*)&g_y[tok*YW + o0 + ob]     = acc[t][0];
        *(unsigned long long*)&g_y[tok*YW + o0 + ob + 2] = acc[t][1];
    }
}

// ---------------- K2: dense-head qkv GEMM (4800 rows x 24, K=96, 3 planes) ----
// grid (75, 3); 192 threads; thread = 4 rows x 2 outputs.
__global__ void __launch_bounds__(192) k_qkvd(const float* __restrict__ x,
                                              const float* __restrict__ W,
                                              const int* __restrict__ a2a) {
    extern __shared__ __align__(16) float sm[];
    float* sX = sm;                  // 64*97
    float* sW = sm + 64*97;          // 96*26
    float* sB = sW + 96*26;          // 24
    int*   sRow = (int*)(sB + 24);   // 64
    const int r0 = blockIdx.x * 64;
    const int p  = blockIdx.y;       // plane: 0=q,1=k,2=v
    const int tid = threadIdx.x;

    if (tid < 64) {
        int r = r0 + tid;
        int b = r / A2LEN, d = r - b*A2LEN;
        sRow[tid] = b*NTOK + a2a[d];
    }
    for (int i = tid; i < 24*96; i += 192) {
        int o = i / 96, k = i - o*96;
        sW[k*26 + o] = W[(96*p + 72 + o)*97 + k];
    }
    if (tid < 24) sB[tid] = W[(96*p + 72 + tid)*97 + 96];
    __syncthreads();
    for (int i = tid; i < 64*96; i += 192) {
        int t = i / 96, k = i - t*96;
        sX[t*97 + k] = x[sRow[t]*96 + k];
    }
    __syncthreads();

    const int tokg = tid & 15;
    const int ob   = (tid >> 4) * 2;
    unsigned long long acc[4];
    {
        unsigned long long bv = *(const unsigned long long*)&sB[ob];
        acc[0] = bv; acc[1] = bv; acc[2] = bv; acc[3] = bv;
    }
#pragma unroll 8
    for (int k = 0; k < 96; k++) {
        unsigned long long w0 = *(const unsigned long long*)&sW[k*26 + ob];
#pragma unroll
        for (int t = 0; t < 4; t++)
            ffma2(acc[t], bcast2(sX[(tokg + 16*t)*97 + k]), w0);
    }
#pragma unroll
    for (int t = 0; t < 4; t++) {
        int r = r0 + tokg + 16*t;
        *(unsigned long long*)&g_yd[p*(NDR*24) + r*24 + ob] = acc[t];
    }
}

// ---------------- K3: sparse L1 attention (m=0, single pass) ------------------
// grid 256 = (b<<3)|(i<<2)|h ; 256 threads; 2 tokens each.
__global__ void __launch_bounds__(256) k_sparse() {
    const int bx = blockIdx.x;
    const int b = bx >> 3;
    const int i = (bx >> 2) & 1;
    const int h = bx & 3;
    const int qb = i*20 + h*5;       // compact channel base (q); k:+40, v:+80
    __shared__ __align__(16) float sK[NTOK*8];
    __shared__ __align__(16) float sV[NTOK*8];
    const int tid = threadIdx.x;
    for (int idx = tid; idx < NTOK*5; idx += 256) {
        int tok = idx / 5, w = idx - tok*5;
        const float* base = &g_y[(b*NTOK + tok)*YW];
        sK[tok*8 + w] = base[40 + qb + w];
        sV[tok*8 + w] = base[80 + qb + w];
    }
    __syncthreads();
    const float scale = 0.44721359549995793f;   // 1/sqrt(5)
    const int* srcp = &g_src[i * 16384];
#pragma unroll
    for (int tt = 0; tt < 2; tt++) {
        const int t = tid + tt*256;
        const float* qp = &g_y[(b*NTOK + t)*YW + qb];
        float q0 = qp[0], q1 = qp[1], q2 = qp[2], q3 = qp[3], q4 = qp[4];
        float l = 0.f, a0 = 0.f, a1 = 0.f, a2 = 0.f, a3 = 0.f, a4 = 0.f;
#pragma unroll 8
        for (int r = 0; r < 32; r++) {
            int src = srcp[r*512 + t];           // coalesced across lanes
            float4 k4 = *(const float4*)&sK[src*8];
            float  k5 = sK[src*8 + 4];
            float s = fabsf(q0 - k4.x) + fabsf(q1 - k4.y) + fabsf(q2 - k4.z)
                    + fabsf(q3 - k4.w) + fabsf(q4 - k5);
            float p = __expf(-s * scale);        // logits <= 0: safe, no max
            l += p;
            float4 v4 = *(const float4*)&sV[src*8];
            float  v5 = sV[src*8 + 4];
            a0 += p*v4.x; a1 += p*v4.y; a2 += p*v4.z; a3 += p*v4.w; a4 += p*v5;
        }
        float inv = 1.0f / l;
        float* op = &g_sp[(b*NTOK + t)*40 + i*20 + h*5];
        op[0] = a0*inv; op[1] = a1*inv; op[2] = a2*inv; op[3] = a3*inv; op[4] = a4*inv;
    }
}

// ---------------- K4: dense a2a L1 attention (m=0, pad key in denom) ----------
// grid (32, 5); 128 threads = 32 d x 4 h.
__global__ void __launch_bounds__(128) k_dense() {
    const int b  = blockIdx.x;
    const int d0 = blockIdx.y * 32;
    __shared__ __align__(16) float sK[A2LEN*24];
    __shared__ __align__(16) float sV[A2LEN*24];
    const int tid = threadIdx.x;
    const int P = NDR * 24;
    for (int idx = tid; idx < A2LEN*24; idx += 128) {
        sK[idx] = g_yd[P   + b*A2LEN*24 + idx];
        sV[idx] = g_yd[2*P + b*A2LEN*24 + idx];
    }
    __syncthreads();
    const int dl = tid >> 2, h = tid & 3;
    const int d = d0 + dl;
    if (d >= A2LEN) return;
    const float* qp = &g_yd[(b*A2LEN + d)*24 + h*6];
    float q[6];
#pragma unroll
    for (int w = 0; w < 6; w++) q[w] = qp[w];
    const float scale = 0.4082482904638631f;    // 1/sqrt(6)
    float l = 0.f;
    float acc[6] = {0.f,0.f,0.f,0.f,0.f,0.f};
#pragma unroll 2
    for (int s = 0; s < A2LEN; s++) {
        const float* kp = &sK[s*24 + h*6];
        float2 ka = *(const float2*)kp;
        float2 kb = *(const float2*)(kp + 2);
        float2 kc = *(const float2*)(kp + 4);
        float ds = fabsf(q[0]-ka.x) + fabsf(q[1]-ka.y) + fabsf(q[2]-kb.x)
                 + fabsf(q[3]-kb.y) + fabsf(q[4]-kc.x) + fabsf(q[5]-kc.y);
        float p = __expf(-ds * scale);
        l += p;
        const float* vp = &sV[s*24 + h*6];
        float2 va = *(const float2*)vp;
        float2 vb = *(const float2*)(vp + 2);
        float2 vc = *(const float2*)(vp + 4);
        acc[0] += p*va.x; acc[1] += p*va.y; acc[2] += p*vb.x;
        acc[3] += p*vb.y; acc[4] += p*vc.x; acc[5] += p*vc.y;
    }
    {   // zero-pad key: denominator only
        float ds = fabsf(q[0]) + fabsf(q[1]) + fabsf(q[2])
                 + fabsf(q[3]) + fabsf(q[4]) + fabsf(q[5]);
        l += __expf(-ds * scale);
    }
    float inv = 1.0f / l;
    float* op = &g_dn[(b*A2LEN + d)*24 + h*6];
#pragma unroll
    for (int w = 0; w < 6; w++) op[w] = acc[w]*inv;
}

// ---------------- K5: out = x + SiLU(b) @ Wf^T + bias --------------------------
__global__ void __launch_bounds__(256) k_final(const float* __restrict__ x,
                                               const float* __restrict__ Wf,
                                               float* __restrict__ out) {
    __shared__ __align__(16) float sY[64*65];   // [t][c] stride 65
    __shared__ __align__(16) float sW[64*98];   // [c][o] stride 98
    __shared__ __align__(16) float sB[96];
    const int t0 = blockIdx.x * 64;
    const int tid = threadIdx.x;

    for (int idx = tid; idx < 64*96; idx += 256) {
        int o = idx / 64, c = idx - o*64;
        sW[c*98 + o] = Wf[o*97 + 32 + c];
    }
    if (tid < 96) sB[tid] = Wf[tid*97 + 96];
    for (int idx = tid; idx < 64*64; idx += 256) {
        int c = idx >> 6, t = idx & 63;
        int tt = t0 + t;
        float v;
        if (c < 40) {
            v = g_sp[tt*40 + c];
        } else {
            int b = tt >> 9, tok = tt & 511;
            int d = g_inv[tok];
            v = (d >= 0) ? g_dn[(b*A2LEN + d)*24 + (c - 40)] : 0.f;
        }
        float sg = 1.0f / (1.0f + __expf(-1.702f * v));
        sY[t*65 + c] = v * sg;
    }
    __syncthreads();

    const int tb = (tid & 15) * 4;
    const int ob = (tid >> 4) * 6;
    unsigned long long acc[4][3];
#pragma unroll
    for (int j = 0; j < 3; j++) {
        unsigned long long bv = *(const unsigned long long*)&sB[ob + 2*j];
        acc[0][j] = bv; acc[1][j] = bv; acc[2][j] = bv; acc[3][j] = bv;
    }
#pragma unroll 8
    for (int k = 0; k < 64; k++) {
        unsigned long long w0 = *(const unsigned long long*)&sW[k*98 + ob];
        unsigned long long w1 = *(const unsigned long long*)&sW[k*98 + ob + 2];
        unsigned long long w2 = *(const unsigned long long*)&sW[k*98 + ob + 4];
#pragma unroll
        for (int t = 0; t < 4; t++) {
            unsigned long long yv = bcast2(sY[(tb + t)*65 + k]);
            ffma2(acc[t][0], yv, w0);
            ffma2(acc[t][1], yv, w1);
            ffma2(acc[t][2], yv, w2);
        }
    }
#pragma unroll
    for (int t = 0; t < 4; t++) {
        int tt = t0 + tb + t;
#pragma unroll
        for (int j = 0; j < 3; j++) {
            unsigned long long xv = *(const unsigned long long*)&x[tt*96 + ob + 2*j];
            *(unsigned long long*)&out[tt*96 + ob + 2*j] = addf2(acc[t][j], xv);
        }
    }
}

// ---------------- launch -------------------------------------------------------
extern "C" void kernel_launch(void* const* d_in, const int* in_sizes, int n_in,
                              void* d_out, int out_size) {
    const float* x    = (const float*)d_in[0];
    const float* wqv  = (const float*)d_in[1];
    const float* wf   = (const float*)d_in[2];
    const int*   coo0 = (const int*)d_in[3];
    const int*   coo1 = (const int*)d_in[4];
    const int*   a2a  = (const int*)d_in[5];
    float*       out  = (float*)d_out;
    (void)in_sizes; (void)n_in; (void)out_size;

    const int smem1 = (64*97 + 96*66 + 64) * sizeof(float);          // 50432
    const int smem2 = (64*97 + 96*26 + 24 + 64) * sizeof(float);     // 35168
    static int inited = 0;
    if (!inited) {
        cudaFuncSetAttribute(k_qkv,  cudaFuncAttributeMaxDynamicSharedMemorySize, smem1);
        cudaFuncSetAttribute(k_qkvd, cudaFuncAttributeMaxDynamicSharedMemorySize, smem2);
        inited = 1;
    }

    k_prep <<<dim3(2, 32), 512>>>(coo0, coo1, a2a);
    k_qkv  <<<dim3(256, 2), 256, smem1>>>(x, wqv);
    k_qkvd <<<dim3(75, 3), 192, smem2>>>(x, wqv, a2a);
    k_sparse<<<256, 256>>>();
    k_dense <<<dim3(32, 5), 128>>>();
    k_final <<<256, 256>>>(x, wf, out);
}